// round 16
// baseline (speedup 1.0000x reference)
#include <cuda_runtime.h>
#include <cuda_fp16.h>
#include <cstdint>

#define D        64
#define H        64
#define TPB      128
#define NW       4
#define MROWS    64              // rows per warp per stage
#define TILE_M   256             // rows per CTA per stage
#define CTAS_PER_SM 2
#define NMAXROW  100000

#define XSTRH    136             // halfs/row; 272 B stride (conflict-free, 16B aligned)
#define BSTRH    136

// dynamic smem layout (bytes)
#define SM_X      0
#define SM_XW     (MROWS * XSTRH * 2)             // 17408 B per warp (64 rows)
#define SM_X_SZ   (NW * SM_XW)                    // 69632
#define SM_B      (SM_X + SM_X_SZ)
#define SM_B_SZ   (H * BSTRH * 2)                 // 17408
#define SM_EA     (SM_B + SM_B_SZ)                // float4[32]: (w1c, w1c, b1, b1) pairs
#define SM_EB     (SM_EA + 512)                   // float2[32]: W2 pairs
#define SM_B2     (SM_EB + 256)
#define SM_IP     (SM_B2 + 16)                    // float[2][NW][64] inv-norm products
#define SM_TOTAL  (SM_IP + 2048)                  // 89872 B -> 2 CTAs/SM

__device__ __align__(16) __half  g_hc_h[NMAXROW * D];
__device__ __align__(16) __half  g_hp_h[NMAXROW * D];
__device__ __align__(16) __half  g_Bimg[H * BSTRH];
__device__ __align__(16) float4  g_EA[32];
__device__ __align__(16) float2  g_EB[32];
__device__ float g_invc[NMAXROW];
__device__ float g_invp[NMAXROW];

// one pass: fp32->fp16 table conversion + fused inv-norm (8 threads/row, 32B each)
__global__ void prep_all(const float* __restrict__ hc, const float* __restrict__ hp,
                         const float* __restrict__ W1, const float* __restrict__ b1,
                         const float* __restrict__ W2, int nc, int np) {
    int t = blockIdx.x * blockDim.x + threadIdx.x;
    int row = t >> 3;
    int l8  = t & 7;
    int nrows = nc + np;
    if (row < nrows) {
        const bool isC = (row < nc);
        int r = isC ? row : row - nc;
        const float4* p4 = (const float4*)((isC ? hc : hp) + (size_t)r * D) + l8 * 2;
        float4 a = p4[0], b = p4[1];
        uint4 w;
        __half2* wp = (__half2*)&w;
        wp[0] = __floats2half2_rn(a.x, a.y);
        wp[1] = __floats2half2_rn(a.z, a.w);
        wp[2] = __floats2half2_rn(b.x, b.y);
        wp[3] = __floats2half2_rn(b.z, b.w);
        *(uint4*)((isC ? g_hc_h : g_hp_h) + (size_t)r * D + l8 * 8) = w;
        float s = a.x*a.x + a.y*a.y + a.z*a.z + a.w*a.w
                + b.x*b.x + b.y*b.y + b.z*b.z + b.w*b.w;
        s += __shfl_xor_sync(0xffffffffu, s, 1);
        s += __shfl_xor_sync(0xffffffffu, s, 2);
        s += __shfl_xor_sync(0xffffffffu, s, 4);
        if (l8 == 0) {
            float iv = 1.0f / fmaxf(sqrtf(s), 1e-12f);
            if (isC) g_invc[r] = iv; else g_invp[r] = iv;
        }
    }
    if (t < H * BSTRH) {
        int n = t / BSTRH, k = t % BSTRH;
        g_Bimg[t] = __float2half_rn((k < 2 * D) ? W1[k * H + n] : 0.0f);
    }
    if (t < 32) {
        int n = 2 * t;
        g_EA[t] = make_float4(W1[2 * D * H + n], W1[2 * D * H + n + 1], b1[n], b1[n + 1]);
        g_EB[t] = make_float2(W2[n], W2[n + 1]);
    }
}

__device__ __forceinline__ uint32_t smem_u32(const void* p) {
    uint32_t a;
    asm("{ .reg .u64 t; cvta.to.shared.u64 t, %1; cvt.u32.u64 %0, t; }" : "=r"(a) : "l"(p));
    return a;
}
__device__ __forceinline__ void cp16(uint32_t saddr, const void* gaddr) {
    asm volatile("cp.async.cg.shared.global [%0], [%1], 16;" :: "r"(saddr), "l"(gaddr));
}
__device__ __forceinline__ void ldsm_x4(uint32_t& r0, uint32_t& r1, uint32_t& r2, uint32_t& r3,
                                        uint32_t addr) {
    asm volatile("ldmatrix.sync.aligned.m8n8.x4.shared.b16 {%0,%1,%2,%3}, [%4];"
                 : "=r"(r0), "=r"(r1), "=r"(r2), "=r"(r3) : "r"(addr));
}
__device__ __forceinline__ void mma_f16(float c[4],
                                        uint32_t a0, uint32_t a1, uint32_t a2, uint32_t a3,
                                        uint32_t b0, uint32_t b1) {
    asm volatile(
        "mma.sync.aligned.m16n8k16.row.col.f32.f16.f16.f32 "
        "{%0,%1,%2,%3}, {%4,%5,%6,%7}, {%8,%9}, {%0,%1,%2,%3};"
        : "+f"(c[0]), "+f"(c[1]), "+f"(c[2]), "+f"(c[3])
        : "r"(a0), "r"(a1), "r"(a2), "r"(a3), "r"(b0), "r"(b1));
}
__device__ __forceinline__ __half2 u2h(uint32_t u) { return *(__half2*)&u; }

__global__ __launch_bounds__(TPB, CTAS_PER_SM)
void edge_mlp_f16_kernel(const int*   __restrict__ src,
                         const int*   __restrict__ dst,
                         const float* __restrict__ b2,
                         float*       __restrict__ out,
                         int E, int ntiles)
{
    extern __shared__ char smem[];
    const uint32_t smem_base = smem_u32(smem);
    float4* sEA = (float4*)(smem + SM_EA);
    float2* sEB = (float2*)(smem + SM_EB);
    float*  sB2 = (float*)(smem + SM_B2);
    float*  sIP = (float*)(smem + SM_IP);        // [2][NW][64]

    const int tid   = threadIdx.x;
    const int wid   = tid >> 5;
    const int lane  = tid & 31;
    const int ngrid = gridDim.x;

    const uint32_t xw = smem_base + SM_X + (uint32_t)wid * SM_XW;

    const int el2   = lane >> 4;
    const int part  = (lane >> 3) & 1;
    const int chunk = lane & 7;

    // ---- stage-0 indices (2 halves of 32 edges) + inv norms ----
    int tile0 = blockIdx.x;
    int ebase0 = tile0 * TILE_M + wid * MROWS;
    int ec0 = ebase0 + lane;      if (ec0 >= E) ec0 = E - 1;
    int ec1 = ebase0 + 32 + lane; if (ec1 >= E) ec1 = E - 1;
    int sv0 = src[ec0], tv0 = dst[ec0];
    int sv1 = src[ec1], tv1 = dst[ec1];
    float iv0 = g_invc[sv0] * g_invp[tv0];
    float iv1 = g_invc[sv1] * g_invp[tv1];

    // ---- B / epilogue-table staging (once) ----
    {
        const char* gB = (const char*)g_Bimg;
        uint32_t dB = smem_base + SM_B;
        #pragma unroll
        for (int i = 0; i < 9; ++i) {
            int c = i * TPB + tid;
            if (c < SM_B_SZ / 16) cp16(dB + (uint32_t)c * 16u, gB + c * 16);
        }
    }
    if (tid < 32) { sEA[tid] = g_EA[tid]; sEB[tid] = g_EB[tid]; }
    if (tid == 0) sB2[0] = b2[0];

    // ---- gather stage 0 (64 rows per warp) ----
    #pragma unroll 8
    for (int i = 0; i < 16; ++i) {
        int ew = 2 * i + el2;
        int si = __shfl_sync(0xffffffffu, sv0, ew);
        int ti = __shfl_sync(0xffffffffu, tv0, ew);
        const __half* g = part ? g_hp_h + (size_t)ti * D + chunk * 8
                               : g_hc_h + (size_t)si * D + chunk * 8;
        cp16(xw + (uint32_t)ew * (XSTRH * 2u) + (uint32_t)(part * 128 + chunk * 16), g);
    }
    #pragma unroll 8
    for (int i = 0; i < 16; ++i) {
        int ew = 2 * i + el2;
        int si = __shfl_sync(0xffffffffu, sv1, ew);
        int ti = __shfl_sync(0xffffffffu, tv1, ew);
        const __half* g = part ? g_hp_h + (size_t)ti * D + chunk * 8
                               : g_hc_h + (size_t)si * D + chunk * 8;
        cp16(xw + (uint32_t)(ew + 32) * (XSTRH * 2u) + (uint32_t)(part * 128 + chunk * 16), g);
    }
    asm volatile("cp.async.commit_group;" ::: "memory");

    sIP[(0 * NW + wid) * 64 + lane]      = iv0;
    sIP[(0 * NW + wid) * 64 + 32 + lane] = iv1;

    // ---- prefetch stage-1 indices ----
    {
        int bb = (tile0 + ngrid) * TILE_M + wid * MROWS + lane;
        int e0c = (bb < E) ? bb : (E - 1);
        int e1c = (bb + 32 < E) ? bb + 32 : (E - 1);
        sv0 = src[e0c]; tv0 = dst[e0c];
        sv1 = src[e1c]; tv1 = dst[e1c];
    }

    asm volatile("cp.async.wait_group 0;" ::: "memory");
    __syncthreads();

    // ---- ldmatrix addresses ----
    const int j = lane >> 3;
    const int r = lane & 7;
    uint32_t aAm[4];
    aAm[0] = xw + (uint32_t)(((j & 1) * 8 + r) * (XSTRH * 2)) + (uint32_t)(j >> 1) * 16u;
    #pragma unroll
    for (int mt = 1; mt < 4; ++mt) aAm[mt] = aAm[0] + (uint32_t)(mt * 16) * (XSTRH * 2u);
    uint32_t aB[4];
    #pragma unroll
    for (int p = 0; p < 4; ++p)
        aB[p] = smem_base + SM_B
              + (uint32_t)((p * 16 + r + (j >> 1) * 8) * (BSTRH * 2))
              + (uint32_t)(j & 1) * 16u;

    const int qrow  = lane >> 2;
    const int qlane = lane & 3;
    const float bias2v = sB2[0];
    int pbuf = 0;

    // =================== stage loop ===================
    for (int tile = tile0; tile < ntiles; tile += ngrid) {
        float acc[4][8][4];
        #pragma unroll
        for (int mt = 0; mt < 4; ++mt)
            #pragma unroll
            for (int nt = 0; nt < 8; ++nt)
                #pragma unroll
                for (int c = 0; c < 4; ++c) acc[mt][nt][c] = 0.f;

        __half2 cdp[4][2];
        #pragma unroll
        for (int mt = 0; mt < 4; ++mt) {
            cdp[mt][0] = __float2half2_rn(0.f);
            cdp[mt][1] = __float2half2_rn(0.f);
        }

        // ---- fused k-loop: ksp covers head col 32B + tail col 32B ----
        #pragma unroll
        for (int ksp = 0; ksp < 4; ++ksp) {
            const uint32_t ko  = (uint32_t)ksp * 32u;
            const uint32_t ko2 = ko + 128u;

            // B fragments (shared across all 4 m-tiles)
            uint32_t bfh[8][2], bft[8][2];
            #pragma unroll
            for (int p = 0; p < 4; ++p) {
                uint32_t r0, r1, r2, r3;
                ldsm_x4(r0, r1, r2, r3, aB[p] + ko);
                bfh[2*p][0] = r0;   bfh[2*p][1] = r1;
                bfh[2*p+1][0] = r2; bfh[2*p+1][1] = r3;
            }
            #pragma unroll
            for (int p = 0; p < 4; ++p) {
                uint32_t r0, r1, r2, r3;
                ldsm_x4(r0, r1, r2, r3, aB[p] + ko2);
                bft[2*p][0] = r0;   bft[2*p][1] = r1;
                bft[2*p+1][0] = r2; bft[2*p+1][1] = r3;
            }

            if (ksp == 0) {
                iv0 = g_invc[sv0] * g_invp[tv0];   // next stage's norm products
                iv1 = g_invc[sv1] * g_invp[tv1];
            }

            #pragma unroll
            for (int mt = 0; mt < 4; ++mt) {
                uint32_t ah[4], at[4];
                ldsm_x4(ah[0], ah[1], ah[2], ah[3], aAm[mt] + ko);
                ldsm_x4(at[0], at[1], at[2], at[3], aAm[mt] + ko2);

                if (ksp == 3 && mt == 3) {
                    // all X reads of this stage issued -> refill buffer
                    if (tile + ngrid < ntiles) {
                        #pragma unroll 8
                        for (int i = 0; i < 16; ++i) {
                            int ew = 2 * i + el2;
                            int si = __shfl_sync(0xffffffffu, sv0, ew);
                            int ti = __shfl_sync(0xffffffffu, tv0, ew);
                            const __half* g = part ? g_hp_h + (size_t)ti * D + chunk * 8
                                                   : g_hc_h + (size_t)si * D + chunk * 8;
                            cp16(xw + (uint32_t)ew * (XSTRH * 2u) + (uint32_t)(part * 128 + chunk * 16), g);
                        }
                        #pragma unroll 8
                        for (int i = 0; i < 16; ++i) {
                            int ew = 2 * i + el2;
                            int si = __shfl_sync(0xffffffffu, sv1, ew);
                            int ti = __shfl_sync(0xffffffffu, tv1, ew);
                            const __half* g = part ? g_hp_h + (size_t)ti * D + chunk * 8
                                                   : g_hc_h + (size_t)si * D + chunk * 8;
                            cp16(xw + (uint32_t)(ew + 32) * (XSTRH * 2u) + (uint32_t)(part * 128 + chunk * 16), g);
                        }
                    }
                    asm volatile("cp.async.commit_group;" ::: "memory");
                    sIP[((pbuf ^ 1) * NW + wid) * 64 + lane]      = iv0;
                    sIP[((pbuf ^ 1) * NW + wid) * 64 + 32 + lane] = iv1;
                    int bb = (tile + 2 * ngrid) * TILE_M + wid * MROWS + lane;
                    int e0c = (bb < E) ? bb : (E - 1);
                    int e1c = (bb + 32 < E) ? bb + 32 : (E - 1);
                    sv0 = src[e0c]; tv0 = dst[e0c];
                    sv1 = src[e1c]; tv1 = dst[e1c];
                }

                // cosine dot partials
                cdp[mt][0] = __hfma2(u2h(ah[0]), u2h(at[0]), cdp[mt][0]);
                cdp[mt][0] = __hfma2(u2h(ah[2]), u2h(at[2]), cdp[mt][0]);
                cdp[mt][1] = __hfma2(u2h(ah[1]), u2h(at[1]), cdp[mt][1]);
                cdp[mt][1] = __hfma2(u2h(ah[3]), u2h(at[3]), cdp[mt][1]);

                #pragma unroll
                for (int nt = 0; nt < 8; ++nt)
                    mma_f16(acc[mt][nt], ah[0], ah[1], ah[2], ah[3], bfh[nt][0], bfh[nt][1]);
                #pragma unroll
                for (int nt = 0; nt < 8; ++nt)
                    mma_f16(acc[mt][nt], at[0], at[1], at[2], at[3], bft[nt][0], bft[nt][1]);
            }
        }

        // ---- finalize cosines: dp butterfly x inv-norm product ----
        float cos4[4][2];
        #pragma unroll
        for (int mt = 0; mt < 4; ++mt)
            #pragma unroll
            for (int h = 0; h < 2; ++h) {
                float2 c = __half22float2(cdp[mt][h]);
                float dp = c.x + c.y;
                dp += __shfl_xor_sync(0xffffffffu, dp, 1);
                dp += __shfl_xor_sync(0xffffffffu, dp, 2);
                float ip = sIP[(pbuf * NW + wid) * 64 + (mt * 16 + h * 8 + qrow)];
                cos4[mt][h] = dp * ip;
            }

        // ---- epilogue: +cos*w1c + b1, relu, dot W2, sigmoid ----
        {
            float zz[4][2];
            #pragma unroll
            for (int mt = 0; mt < 4; ++mt) { zz[mt][0] = 0.f; zz[mt][1] = 0.f; }
            #pragma unroll
            for (int nt = 0; nt < 8; ++nt) {
                float4 ea = sEA[nt * 4 + qlane];
                float2 eb = sEB[nt * 4 + qlane];
                #pragma unroll
                for (int mt = 0; mt < 4; ++mt)
                    #pragma unroll
                    for (int rr = 0; rr < 2; ++rr) {
                        float cR = cos4[mt][rr];
                        float v0 = acc[mt][nt][2*rr]     + fmaf(cR, ea.x, ea.z);
                        float v1 = acc[mt][nt][2*rr + 1] + fmaf(cR, ea.y, ea.w);
                        zz[mt][rr] = fmaf(fmaxf(v0, 0.f), eb.x, zz[mt][rr]);
                        zz[mt][rr] = fmaf(fmaxf(v1, 0.f), eb.y, zz[mt][rr]);
                    }
            }
            const int eb0 = tile * TILE_M + wid * MROWS;
            #pragma unroll
            for (int mt = 0; mt < 4; ++mt)
                #pragma unroll
                for (int rr = 0; rr < 2; ++rr) {
                    float z = zz[mt][rr];
                    z += __shfl_xor_sync(0xffffffffu, z, 1);
                    z += __shfl_xor_sync(0xffffffffu, z, 2);
                    if (qlane == 0) {
                        int eo = eb0 + mt * 16 + rr * 8 + qrow;
                        if (eo < E) {
                            float ez = __expf(-(z + bias2v));
                            out[eo] = __fdividef(1.0f, 1.0f + ez);
                        }
                    }
                }
        }

        asm volatile("cp.async.wait_group 0;" ::: "memory");
        __syncwarp();
        pbuf ^= 1;
    }
}

extern "C" void kernel_launch(void* const* d_in, const int* in_sizes, int n_in,
                              void* d_out, int out_size)
{
    const float* hc  = (const float*)d_in[0];
    const float* hp  = (const float*)d_in[1];
    const int*   src = (const int*)  d_in[2];
    const int*   dst = (const int*)  d_in[3];
    const float* W1  = (const float*)d_in[4];
    const float* b1  = (const float*)d_in[5];
    const float* W2  = (const float*)d_in[6];
    const float* b2  = (const float*)d_in[7];
    float* out = (float*)d_out;

    static int nsm = 0;
    if (!nsm) {
        cudaDeviceGetAttribute(&nsm, cudaDevAttrMultiProcessorCount, 0);
        cudaFuncSetAttribute(edge_mlp_f16_kernel,
                             cudaFuncAttributeMaxDynamicSharedMemorySize, SM_TOTAL);
    }

    int E  = in_sizes[2];
    int nc = in_sizes[0] / D;
    int np = in_sizes[1] / D;

    int pthreads = (nc + np) * 8;
    if (pthreads < H * BSTRH) pthreads = H * BSTRH;
    prep_all<<<(pthreads + 255) / 256, 256>>>(hc, hp, W1, b1, W2, nc, np);

    int ntiles = (E + TILE_M - 1) / TILE_M;
    int ngrid  = nsm * CTAS_PER_SM;
    if (ngrid > ntiles) ngrid = ntiles;
    edge_mlp_f16_kernel<<<ngrid, TPB, SM_TOTAL>>>(src, dst, b2, out, E, ntiles);
}

// round 17
// speedup vs baseline: 1.0658x; 1.0658x over previous
#include <cuda_runtime.h>
#include <cuda_fp16.h>
#include <cstdint>

#define D        64
#define H        64
#define TPB      128
#define NW       4
#define TILE_M   128
#define CTAS_PER_SM 4
#define NMAXROW  100000

#define XSTRH    136             // halfs/row; 272 B stride (conflict-free, 16B aligned)
#define BSTRH    136

// dynamic smem layout (bytes)
#define SM_X      0
#define SM_XW     (32 * XSTRH * 2)                // 8704 B per warp (32 rows)
#define SM_X_SZ   (NW * SM_XW)                    // 34816
#define SM_B      (SM_X + SM_X_SZ)
#define SM_B_SZ   (H * BSTRH * 2)                 // 17408
#define SM_EA     (SM_B + SM_B_SZ)                // float4[32]: (w1c, w1c, b1, b1) pairs
#define SM_EB     (SM_EA + 512)                   // float2[32]: W2 pairs
#define SM_B2     (SM_EB + 256)
#define SM_TOTAL  (SM_B2 + 16)                    // ~53 KB -> 4 CTAs/SM (212 KB)

__device__ __align__(16) __half  g_hc_h[NMAXROW * D];
__device__ __align__(16) __half  g_hp_h[NMAXROW * D];
__device__ __align__(16) __half  g_Bimg[H * BSTRH];
__device__ __align__(16) float4  g_EA[32];
__device__ __align__(16) float2  g_EB[32];
__device__ float g_invc[NMAXROW];
__device__ float g_invp[NMAXROW];

// one pass: fp32->fp16 table conversion + fused inv-norm (8 threads/row, 32B each)
__global__ void prep_all(const float* __restrict__ hc, const float* __restrict__ hp,
                         const float* __restrict__ W1, const float* __restrict__ b1,
                         const float* __restrict__ W2, int nc, int np) {
    int t = blockIdx.x * blockDim.x + threadIdx.x;
    int row = t >> 3;
    int l8  = t & 7;
    int nrows = nc + np;
    if (row < nrows) {
        const bool isC = (row < nc);
        int r = isC ? row : row - nc;
        const float4* p4 = (const float4*)((isC ? hc : hp) + (size_t)r * D) + l8 * 2;
        float4 a = p4[0], b = p4[1];
        uint4 w;
        __half2* wp = (__half2*)&w;
        wp[0] = __floats2half2_rn(a.x, a.y);
        wp[1] = __floats2half2_rn(a.z, a.w);
        wp[2] = __floats2half2_rn(b.x, b.y);
        wp[3] = __floats2half2_rn(b.z, b.w);
        *(uint4*)((isC ? g_hc_h : g_hp_h) + (size_t)r * D + l8 * 8) = w;
        float s = a.x*a.x + a.y*a.y + a.z*a.z + a.w*a.w
                + b.x*b.x + b.y*b.y + b.z*b.z + b.w*b.w;
        s += __shfl_xor_sync(0xffffffffu, s, 1);
        s += __shfl_xor_sync(0xffffffffu, s, 2);
        s += __shfl_xor_sync(0xffffffffu, s, 4);
        if (l8 == 0) {
            float iv = 1.0f / fmaxf(sqrtf(s), 1e-12f);
            if (isC) g_invc[r] = iv; else g_invp[r] = iv;
        }
    }
    if (t < H * BSTRH) {
        int n = t / BSTRH, k = t % BSTRH;
        g_Bimg[t] = __float2half_rn((k < 2 * D) ? W1[k * H + n] : 0.0f);
    }
    if (t < 32) {
        int n = 2 * t;
        g_EA[t] = make_float4(W1[2 * D * H + n], W1[2 * D * H + n + 1], b1[n], b1[n + 1]);
        g_EB[t] = make_float2(W2[n], W2[n + 1]);
    }
}

__device__ __forceinline__ uint32_t smem_u32(const void* p) {
    uint32_t a;
    asm("{ .reg .u64 t; cvta.to.shared.u64 t, %1; cvt.u32.u64 %0, t; }" : "=r"(a) : "l"(p));
    return a;
}
__device__ __forceinline__ void cp16(uint32_t saddr, const void* gaddr) {
    asm volatile("cp.async.cg.shared.global [%0], [%1], 16;" :: "r"(saddr), "l"(gaddr));
}
__device__ __forceinline__ void ldsm_x4(uint32_t& r0, uint32_t& r1, uint32_t& r2, uint32_t& r3,
                                        uint32_t addr) {
    asm volatile("ldmatrix.sync.aligned.m8n8.x4.shared.b16 {%0,%1,%2,%3}, [%4];"
                 : "=r"(r0), "=r"(r1), "=r"(r2), "=r"(r3) : "r"(addr));
}
// fp16-accumulate MMA: c/d are 2x b32 (4 f16)
__device__ __forceinline__ void mma_f16acc(uint32_t c[2],
                                           uint32_t a0, uint32_t a1, uint32_t a2, uint32_t a3,
                                           uint32_t b0, uint32_t b1) {
    asm volatile(
        "mma.sync.aligned.m16n8k16.row.col.f16.f16.f16.f16 "
        "{%0,%1}, {%2,%3,%4,%5}, {%6,%7}, {%0,%1};"
        : "+r"(c[0]), "+r"(c[1])
        : "r"(a0), "r"(a1), "r"(a2), "r"(a3), "r"(b0), "r"(b1));
}
__device__ __forceinline__ __half2 u2h(uint32_t u) { return *(__half2*)&u; }

__global__ __launch_bounds__(TPB, CTAS_PER_SM)
void edge_mlp_f16_kernel(const int*   __restrict__ src,
                         const int*   __restrict__ dst,
                         const float* __restrict__ b2,
                         float*       __restrict__ out,
                         int E, int ntiles)
{
    extern __shared__ char smem[];
    const uint32_t smem_base = smem_u32(smem);
    float4* sEA = (float4*)(smem + SM_EA);
    float2* sEB = (float2*)(smem + SM_EB);
    float*  sB2 = (float*)(smem + SM_B2);

    const int tid   = threadIdx.x;
    const int wid   = tid >> 5;
    const int lane  = tid & 31;
    const int ngrid = gridDim.x;

    const uint32_t xw = smem_base + SM_X + (uint32_t)wid * SM_XW;

    const int el2   = lane >> 4;
    const int part  = (lane >> 3) & 1;
    const int chunk = lane & 7;

    // ---- stage-0 indices + inv-norm product (register-resident) ----
    int tile0 = blockIdx.x;
    int ec = tile0 * TILE_M + wid * 32 + lane; if (ec >= E) ec = E - 1;
    int sv = src[ec], tv = dst[ec];
    float ivcur = g_invc[sv] * g_invp[tv];
    float ivnext;

    // ---- B / epilogue-table staging (once) ----
    {
        const char* gB = (const char*)g_Bimg;
        uint32_t dB = smem_base + SM_B;
        #pragma unroll
        for (int i = 0; i < 9; ++i) {
            int c = i * TPB + tid;
            if (c < SM_B_SZ / 16) cp16(dB + (uint32_t)c * 16u, gB + c * 16);
        }
    }
    if (tid < 32) { sEA[tid] = g_EA[tid]; sEB[tid] = g_EB[tid]; }
    if (tid == 0) sB2[0] = b2[0];

    // ---- gather stage 0 ----
    #pragma unroll 8
    for (int i = 0; i < 16; ++i) {
        int ew = 2 * i + el2;
        int si = __shfl_sync(0xffffffffu, sv, ew);
        int ti = __shfl_sync(0xffffffffu, tv, ew);
        const __half* g = part ? g_hp_h + (size_t)ti * D + chunk * 8
                               : g_hc_h + (size_t)si * D + chunk * 8;
        cp16(xw + (uint32_t)ew * (XSTRH * 2u) + (uint32_t)(part * 128 + chunk * 16), g);
    }
    asm volatile("cp.async.commit_group;" ::: "memory");

    // ---- prefetch stage-1 indices ----
    {
        int bb = (tile0 + ngrid) * TILE_M + wid * 32 + lane;
        int ecl = (bb < E) ? bb : (E - 1);
        sv = src[ecl]; tv = dst[ecl];
    }

    asm volatile("cp.async.wait_group 0;" ::: "memory");
    __syncthreads();

    // ---- ldmatrix addresses ----
    const int j = lane >> 3;
    const int r = lane & 7;
    const uint32_t aA0 = xw + (uint32_t)(((j & 1) * 8 + r) * (XSTRH * 2)) + (uint32_t)(j >> 1) * 16u;
    const uint32_t aA1 = aA0 + 16u * (XSTRH * 2u);
    uint32_t aB[4];
    #pragma unroll
    for (int p = 0; p < 4; ++p)
        aB[p] = smem_base + SM_B
              + (uint32_t)((p * 16 + r + (j >> 1) * 8) * (BSTRH * 2))
              + (uint32_t)(j & 1) * 16u;

    const int qrow  = lane >> 2;
    const int qlane = lane & 3;
    const float bias2v = sB2[0];

    // =================== stage loop ===================
    for (int tile = tile0; tile < ntiles; tile += ngrid) {
        uint32_t acc[2][8][2];
        #pragma unroll
        for (int mt = 0; mt < 2; ++mt)
            #pragma unroll
            for (int nt = 0; nt < 8; ++nt) { acc[mt][nt][0] = 0u; acc[mt][nt][1] = 0u; }

        __half2 cdp[2][2];
        #pragma unroll
        for (int mt = 0; mt < 2; ++mt) {
            cdp[mt][0] = __float2half2_rn(0.f);
            cdp[mt][1] = __float2half2_rn(0.f);
        }

        // ---- fused k-loop: pairs (ks, ks+4) = (head cols, tail cols) ----
        #pragma unroll
        for (int ksp = 0; ksp < 4; ++ksp) {
            const uint32_t ko  = (uint32_t)ksp * 32u;
            const uint32_t ko2 = ko + 128u;

            uint32_t ah[2][4], at[2][4];
            ldsm_x4(ah[0][0], ah[0][1], ah[0][2], ah[0][3], aA0 + ko);
            ldsm_x4(ah[1][0], ah[1][1], ah[1][2], ah[1][3], aA1 + ko);
            ldsm_x4(at[0][0], at[0][1], at[0][2], at[0][3], aA0 + ko2);
            ldsm_x4(at[1][0], at[1][1], at[1][2], at[1][3], aA1 + ko2);

            if (ksp == 0) {
                ivnext = g_invc[sv] * g_invp[tv];   // next stage's norm product
            }
            if (ksp == 3) {
                if (tile + ngrid < ntiles) {
                    #pragma unroll 8
                    for (int i = 0; i < 16; ++i) {
                        int ew = 2 * i + el2;
                        int si = __shfl_sync(0xffffffffu, sv, ew);
                        int ti = __shfl_sync(0xffffffffu, tv, ew);
                        const __half* g = part ? g_hp_h + (size_t)ti * D + chunk * 8
                                               : g_hc_h + (size_t)si * D + chunk * 8;
                        cp16(xw + (uint32_t)ew * (XSTRH * 2u) + (uint32_t)(part * 128 + chunk * 16), g);
                    }
                }
                asm volatile("cp.async.commit_group;" ::: "memory");
                int bb = (tile + 2 * ngrid) * TILE_M + wid * 32 + lane;
                int ecl = (bb < E) ? bb : (E - 1);
                sv = src[ecl]; tv = dst[ecl];
            }

            // cosine dot partials
            #pragma unroll
            for (int mt = 0; mt < 2; ++mt) {
                cdp[mt][0] = __hfma2(u2h(ah[mt][0]), u2h(at[mt][0]), cdp[mt][0]);
                cdp[mt][0] = __hfma2(u2h(ah[mt][2]), u2h(at[mt][2]), cdp[mt][0]);
                cdp[mt][1] = __hfma2(u2h(ah[mt][1]), u2h(at[mt][1]), cdp[mt][1]);
                cdp[mt][1] = __hfma2(u2h(ah[mt][3]), u2h(at[mt][3]), cdp[mt][1]);
            }

            // B fragments + MMAs: head k-step
            {
                uint32_t bf[8][2];
                #pragma unroll
                for (int p = 0; p < 4; ++p) {
                    uint32_t r0, r1, r2, r3;
                    ldsm_x4(r0, r1, r2, r3, aB[p] + ko);
                    bf[2*p][0] = r0;   bf[2*p][1] = r1;
                    bf[2*p+1][0] = r2; bf[2*p+1][1] = r3;
                }
                #pragma unroll
                for (int nt = 0; nt < 8; ++nt) {
                    mma_f16acc(acc[0][nt], ah[0][0], ah[0][1], ah[0][2], ah[0][3], bf[nt][0], bf[nt][1]);
                    mma_f16acc(acc[1][nt], ah[1][0], ah[1][1], ah[1][2], ah[1][3], bf[nt][0], bf[nt][1]);
                }
            }
            // tail k-step
            {
                uint32_t bf[8][2];
                #pragma unroll
                for (int p = 0; p < 4; ++p) {
                    uint32_t r0, r1, r2, r3;
                    ldsm_x4(r0, r1, r2, r3, aB[p] + ko2);
                    bf[2*p][0] = r0;   bf[2*p][1] = r1;
                    bf[2*p+1][0] = r2; bf[2*p+1][1] = r3;
                }
                #pragma unroll
                for (int nt = 0; nt < 8; ++nt) {
                    mma_f16acc(acc[0][nt], at[0][0], at[0][1], at[0][2], at[0][3], bf[nt][0], bf[nt][1]);
                    mma_f16acc(acc[1][nt], at[1][0], at[1][1], at[1][2], at[1][3], bf[nt][0], bf[nt][1]);
                }
            }
        }

        // ---- finalize cosines: dp butterfly x inv-norm product (via shfl) ----
        float cos4[2][2];
        #pragma unroll
        for (int mt = 0; mt < 2; ++mt)
            #pragma unroll
            for (int h = 0; h < 2; ++h) {
                float2 c = __half22float2(cdp[mt][h]);
                float dp = c.x + c.y;
                dp += __shfl_xor_sync(0xffffffffu, dp, 1);
                dp += __shfl_xor_sync(0xffffffffu, dp, 2);
                float ip = __shfl_sync(0xffffffffu, ivcur, mt * 16 + h * 8 + qrow);
                cos4[mt][h] = dp * ip;
            }
        ivcur = ivnext;

        // ---- epilogue: +cos*w1c + b1, relu, dot W2, sigmoid ----
        {
            float zz[2][2] = {{0.f, 0.f}, {0.f, 0.f}};
            #pragma unroll
            for (int nt = 0; nt < 8; ++nt) {
                float4 ea = sEA[nt * 4 + qlane];
                float2 eb = sEB[nt * 4 + qlane];
                #pragma unroll
                for (int mt = 0; mt < 2; ++mt)
                    #pragma unroll
                    for (int rr = 0; rr < 2; ++rr) {
                        float2 hv = __half22float2(u2h(acc[mt][nt][rr]));
                        float cR = cos4[mt][rr];
                        float v0 = hv.x + fmaf(cR, ea.x, ea.z);
                        float v1 = hv.y + fmaf(cR, ea.y, ea.w);
                        zz[mt][rr] = fmaf(fmaxf(v0, 0.f), eb.x, zz[mt][rr]);
                        zz[mt][rr] = fmaf(fmaxf(v1, 0.f), eb.y, zz[mt][rr]);
                    }
            }
            const int ebase = tile * TILE_M + wid * 32;
            #pragma unroll
            for (int mt = 0; mt < 2; ++mt)
                #pragma unroll
                for (int rr = 0; rr < 2; ++rr) {
                    float z = zz[mt][rr];
                    z += __shfl_xor_sync(0xffffffffu, z, 1);
                    z += __shfl_xor_sync(0xffffffffu, z, 2);
                    if (qlane == 0) {
                        int eo = ebase + mt * 16 + rr * 8 + qrow;
                        if (eo < E) {
                            float ez = __expf(-(z + bias2v));
                            out[eo] = __fdividef(1.0f, 1.0f + ez);
                        }
                    }
                }
        }

        asm volatile("cp.async.wait_group 0;" ::: "memory");
        __syncwarp();
    }
}

extern "C" void kernel_launch(void* const* d_in, const int* in_sizes, int n_in,
                              void* d_out, int out_size)
{
    const float* hc  = (const float*)d_in[0];
    const float* hp  = (const float*)d_in[1];
    const int*   src = (const int*)  d_in[2];
    const int*   dst = (const int*)  d_in[3];
    const float* W1  = (const float*)d_in[4];
    const float* b1  = (const float*)d_in[5];
    const float* W2  = (const float*)d_in[6];
    const float* b2  = (const float*)d_in[7];
    float* out = (float*)d_out;

    static int nsm = 0;
    if (!nsm) {
        cudaDeviceGetAttribute(&nsm, cudaDevAttrMultiProcessorCount, 0);
        cudaFuncSetAttribute(edge_mlp_f16_kernel,
                             cudaFuncAttributeMaxDynamicSharedMemorySize, SM_TOTAL);
    }

    int E  = in_sizes[2];
    int nc = in_sizes[0] / D;
    int np = in_sizes[1] / D;

    int pthreads = (nc + np) * 8;
    if (pthreads < H * BSTRH) pthreads = H * BSTRH;
    prep_all<<<(pthreads + 255) / 256, 256>>>(hc, hp, W1, b1, W2, nc, np);

    int ntiles = (E + TILE_M - 1) / TILE_M;
    int ngrid  = nsm * CTAS_PER_SM;
    if (ngrid > ntiles) ngrid = ntiles;
    edge_mlp_f16_kernel<<<ngrid, TPB, SM_TOTAL>>>(src, dst, b2, out, E, ntiles);
}